// round 9
// baseline (speedup 1.0000x reference)
#include <cuda_runtime.h>
#include <cstdint>

#define N_AGENTS 8192

__global__ void __launch_bounds__(256)
rollout_policy_kernel(const float* __restrict__ x,
                      const float* __restrict__ u,
                      float* __restrict__ out)
{
    const int gtid  = blockIdx.x * blockDim.x + threadIdx.x;
    const int agent = gtid >> 5;           // one warp per agent
    const int lane  = threadIdx.x & 31;
    if (agent >= N_AGENTS) return;

    // x is (2N, 3) row-major: agents rows [0,N), goals rows [N,2N); cols 0,1 used.
    const float ax = x[3 * agent];
    const float ay = x[3 * agent + 1];
    const float*  gbase  = x + 3 * N_AGENTS;          // 16B-aligned (x + 96KB)
    const float4* gbase4 = reinterpret_cast<const float4*>(gbase);

    // Lane handles 4-goal chunks c = lane + 32k, k = 0..63, goals 4c..4c+3.
    // 4 goals = 12 floats = 3 float4 loads (coalesced across the warp).
    // Two accumulators (A: even k, B: odd k) for ILP; each sees ascending
    // goal indices, so strict < keeps first occurrence within each.
    float bestA = __int_as_float(0x7f800000); int biA = 0;
    float bestB = __int_as_float(0x7f800000); int biB = 0;

    const float4* p = gbase4 + 3 * lane;
    int g = 4 * lane;

    #pragma unroll 4
    for (int k = 0; k < 64; k += 2) {
        // ---- chunk A (goal base g) ----
        {
            float4 v0 = p[0], v1 = p[1], v2 = p[2];
            // v0=(x0,y0,z0,x1) v1=(y1,z1,x2,y2) v2=(z2,x3,y3,z3)
            float d0 = fabsf(ax - v0.x) + fabsf(ay - v0.y);
            float d1 = fabsf(ax - v0.w) + fabsf(ay - v1.x);
            float d2 = fabsf(ax - v1.z) + fabsf(ay - v1.w);
            float d3 = fabsf(ax - v2.y) + fabsf(ay - v2.z);
            float m01 = fminf(d0, d1); int i01 = (d1 < d0) ? g + 1 : g;
            float m23 = fminf(d2, d3); int i23 = (d3 < d2) ? g + 3 : g + 2;
            float m   = fminf(m01, m23);
            int   im  = (m23 < m01) ? i23 : i01;
            if (m < bestA) { bestA = m; biA = im; }
        }
        // ---- chunk B (goal base g + 128) ----
        {
            float4 w0 = p[96], w1 = p[97], w2 = p[98];
            int h = g + 128;
            float d0 = fabsf(ax - w0.x) + fabsf(ay - w0.y);
            float d1 = fabsf(ax - w0.w) + fabsf(ay - w1.x);
            float d2 = fabsf(ax - w1.z) + fabsf(ay - w1.w);
            float d3 = fabsf(ax - w2.y) + fabsf(ay - w2.z);
            float m01 = fminf(d0, d1); int i01 = (d1 < d0) ? h + 1 : h;
            float m23 = fminf(d2, d3); int i23 = (d3 < d2) ? h + 3 : h + 2;
            float m   = fminf(m01, m23);
            int   im  = (m23 < m01) ? i23 : i01;
            if (m < bestB) { bestB = m; biB = im; }
        }
        p += 192;           // 2 chunks * 32 lanes * 3 float4
        g += 256;           // 2 chunks * 32 lanes * 4 goals
    }

    // Merge accumulators: lexicographic (dist, idx) — first-occurrence safe.
    float best = bestA; int bi = biA;
    if (bestB < best || (bestB == best && biB < bi)) { best = bestB; bi = biB; }

    // Warp reduction: lexicographic (dist, idx) min == global first argmin.
    const unsigned mask = 0xffffffffu;
    #pragma unroll
    for (int off = 16; off; off >>= 1) {
        float od = __shfl_xor_sync(mask, best, off);
        int   oi = __shfl_xor_sync(mask, bi,   off);
        if (od < best || (od == best && oi < bi)) { best = od; bi = oi; }
    }

    if (lane == 0) {
        float gx = gbase[3 * bi];
        float gy = gbase[3 * bi + 1];
        float dx = gx - ax;
        float dy = gy - ay;

        // probs = [dx>0, dx<0, dy>0, dy<0, (dx==0)&(dy==0)]; cdf = cumsum
        float c0 = (dx > 0.0f) ? 1.0f : 0.0f;
        float c1 = c0 + ((dx < 0.0f) ? 1.0f : 0.0f);
        float c2 = c1 + ((dy > 0.0f) ? 1.0f : 0.0f);
        float c3 = c2 + ((dy < 0.0f) ? 1.0f : 0.0f);
        float c4 = c3 + ((dx == 0.0f && dy == 0.0f) ? 1.0f : 0.0f);

        float t = u[agent] * c4;

        int act = 4;
        if      (c0 >= t) act = 0;
        else if (c1 >= t) act = 1;
        else if (c2 >= t) act = 2;
        else if (c3 >= t) act = 3;

        out[agent] = (float)act;     // output dtype is float32
    }
}

extern "C" void kernel_launch(void* const* d_in, const int* in_sizes, int n_in,
                              void* d_out, int out_size)
{
    // Size-driven binding (element counts): x = 6*N, u = N.
    const float* x = nullptr;
    const float* u = nullptr;
    for (int i = 0; i < n_in; i++) {
        if (in_sizes[i] == 6 * N_AGENTS)      x = (const float*)d_in[i];
        else if (in_sizes[i] == N_AGENTS)     u = (const float*)d_in[i];
    }
    if (!x) x = (const float*)d_in[0];
    if (!u) u = (const float*)d_in[n_in > 1 ? 1 : 0];

    float* out = (float*)d_out;

    const int threads = 256;                          // 8 agents per block
    const int blocks  = (N_AGENTS * 32) / threads;    // 1024
    rollout_policy_kernel<<<blocks, threads>>>(x, u, out);
    (void)out_size;
}

// round 12
// speedup vs baseline: 1.5563x; 1.5563x over previous
#include <cuda_runtime.h>
#include <cstdint>

#define N_AGENTS 8192
#define AG 2                      // agents per warp
#define NWARPS (N_AGENTS / AG)    // 4096 warps
#define ITERS (N_AGENTS / 2 / 32) // 128 float4 (goal-pair) iters per lane

// Scratch: goals packed as (x0,y0,x1,y1) per float4 — 2 goals / 16B. 64 KB.
__device__ float4 g_goals4[N_AGENTS / 2];

__global__ void __launch_bounds__(256)
pack_goals_kernel(const float* __restrict__ x)
{
    const int g = blockIdx.x * blockDim.x + threadIdx.x;
    if (g < N_AGENTS) {
        const float* gb = x + 3 * N_AGENTS;
        // float2 view of the float4 array: 8B-aligned element writes
        reinterpret_cast<float2*>(g_goals4)[g] =
            make_float2(gb[3 * g], gb[3 * g + 1]);
    }
}

__global__ void __launch_bounds__(256)
rollout_policy_kernel(const float* __restrict__ x,
                      const float* __restrict__ u,
                      float* __restrict__ out)
{
    const int gtid = blockIdx.x * blockDim.x + threadIdx.x;
    const int warp = gtid >> 5;
    const int lane = threadIdx.x & 31;
    if (warp >= NWARPS) return;

    const int a0 = warp * AG;          // this warp's two agents
    const float ax0 = x[3 * a0],       ay0 = x[3 * a0 + 1];
    const float ax1 = x[3 * (a0 + 1)], ay1 = x[3 * (a0 + 1) + 1];

    const float INF = __int_as_float(0x7f800000);
    float b0 = INF, b1 = INF;
    int   i0 = 0,   i1 = 0;

    // Lane scans goal-pairs p = lane + 32*it (coalesced LDG.128, ascending
    // goal indices per lane -> strict < keeps first occurrence per lane).
    const float4* gp = g_goals4 + lane;

    #pragma unroll 8
    for (int it = 0; it < ITERS; it++) {
        const float4 v = gp[it * 32];
        const int g = 2 * (lane + 32 * it);   // goals g (v.x,v.y), g+1 (v.z,v.w)

        // agent 0
        {
            float d0 = fabsf(ax0 - v.x) + fabsf(ay0 - v.y);
            float d1 = fabsf(ax0 - v.z) + fabsf(ay0 - v.w);
            float m  = fminf(d0, d1);
            int   im = (d1 < d0) ? g + 1 : g;     // tie -> lower index
            if (m < b0) { b0 = m; i0 = im; }
        }
        // agent 1
        {
            float d0 = fabsf(ax1 - v.x) + fabsf(ay1 - v.y);
            float d1 = fabsf(ax1 - v.z) + fabsf(ay1 - v.w);
            float m  = fminf(d0, d1);
            int   im = (d1 < d0) ? g + 1 : g;
            if (m < b1) { b1 = m; i1 = im; }
        }
    }

    // Per-agent warp reduction + policy. Lexicographic (dist, idx) min ==
    // global first-occurrence argmin.
    const unsigned mask = 0xffffffffu;

    #pragma unroll
    for (int a = 0; a < AG; a++) {
        float best = (a == 0) ? b0 : b1;
        int   bi   = (a == 0) ? i0 : i1;

        #pragma unroll
        for (int off = 16; off; off >>= 1) {
            float od = __shfl_xor_sync(mask, best, off);
            int   oi = __shfl_xor_sync(mask, bi,   off);
            if (od < best || (od == best && oi < bi)) { best = od; bi = oi; }
        }

        if (lane == a) {
            const int agent = a0 + a;
            const float2 gsel = reinterpret_cast<const float2*>(g_goals4)[bi];
            float dx = gsel.x - ((a == 0) ? ax0 : ax1);
            float dy = gsel.y - ((a == 0) ? ay0 : ay1);

            float c0 = (dx > 0.0f) ? 1.0f : 0.0f;
            float c1 = c0 + ((dx < 0.0f) ? 1.0f : 0.0f);
            float c2 = c1 + ((dy > 0.0f) ? 1.0f : 0.0f);
            float c3 = c2 + ((dy < 0.0f) ? 1.0f : 0.0f);
            float c4 = c3 + ((dx == 0.0f && dy == 0.0f) ? 1.0f : 0.0f);

            float t = u[agent] * c4;

            int act = 4;
            if      (c0 >= t) act = 0;
            else if (c1 >= t) act = 1;
            else if (c2 >= t) act = 2;
            else if (c3 >= t) act = 3;

            out[agent] = (float)act;     // output dtype is float32
        }
    }
}

extern "C" void kernel_launch(void* const* d_in, const int* in_sizes, int n_in,
                              void* d_out, int out_size)
{
    // Size-driven binding (element counts): x = 6*N, u = N.
    const float* x = nullptr;
    const float* u = nullptr;
    for (int i = 0; i < n_in; i++) {
        if (in_sizes[i] == 6 * N_AGENTS)      x = (const float*)d_in[i];
        else if (in_sizes[i] == N_AGENTS)     u = (const float*)d_in[i];
    }
    if (!x) x = (const float*)d_in[0];
    if (!u) u = (const float*)d_in[n_in > 1 ? 1 : 0];

    float* out = (float*)d_out;

    pack_goals_kernel<<<N_AGENTS / 256, 256>>>(x);
    rollout_policy_kernel<<<(NWARPS * 32) / 256, 256>>>(x, u, out);
    (void)out_size;
}

// round 14
// speedup vs baseline: 1.5702x; 1.0089x over previous
#include <cuda_runtime.h>
#include <cstdint>

#define N_AGENTS 8192
#define NPAIRS   (N_AGENTS / 2)       // 4096 float4 goal-pairs
#define AGW      4                    // agents per warp
#define SPLITS   4                    // goal-range splits per agent
#define THREADS  256                  // 8 warps: 2 agent-groups x 4 splits
#define AGB      8                    // agents per block
#define NBLOCKS  (N_AGENTS / AGB)     // 1024
#define PAIRS_PER_SPLIT (NPAIRS / SPLITS)       // 1024
#define ITERS    (PAIRS_PER_SPLIT / 32)         // 32

// Goals packed (x0,y0,x1,y1): 2 goals per float4. 64 KB scratch.
__device__ float4 g_goals4[NPAIRS];

__global__ void __launch_bounds__(256)
pack_goals_kernel(const float* __restrict__ x)
{
    const int g = blockIdx.x * blockDim.x + threadIdx.x;
    if (g < N_AGENTS) {
        const float* gb = x + 3 * N_AGENTS;
        reinterpret_cast<float2*>(g_goals4)[g] =
            make_float2(gb[3 * g], gb[3 * g + 1]);
    }
}

__global__ void __launch_bounds__(THREADS, 6)
rollout_policy_kernel(const float* __restrict__ x,
                      const float* __restrict__ u,
                      float* __restrict__ out)
{
    __shared__ float sd[2 * AGW * SPLITS];   // [group][agent][split] partial dist
    __shared__ int   si[2 * AGW * SPLITS];   // partial argmin index

    const int tid   = threadIdx.x;
    const int lane  = tid & 31;
    const int warp  = tid >> 5;              // 0..7
    const int group = warp >> 2;             // 0..1
    const int split = warp & 3;              // 0..3

    const int a0 = blockIdx.x * AGB + group * AGW;   // first of this warp's 4 agents

    // Agent coords (x is (2N,3) row-major, cols 0/1)
    float ax0 = x[3 * a0],       ay0 = x[3 * a0 + 1];
    float ax1 = x[3 * (a0 + 1)], ay1 = x[3 * (a0 + 1) + 1];
    float ax2 = x[3 * (a0 + 2)], ay2 = x[3 * (a0 + 2) + 1];
    float ax3 = x[3 * (a0 + 3)], ay3 = x[3 * (a0 + 3) + 1];

    const float INF = __int_as_float(0x7f800000);
    float b0 = INF, b1 = INF, b2 = INF, b3 = INF;
    int   i0 = 0,   i1 = 0,   i2 = 0,   i3 = 0;

    // Lane scans pair indices p = split*1024 + lane + 32*it (coalesced LDG.128,
    // ascending per lane -> strict < keeps first occurrence per lane).
    const float4* gp = g_goals4 + split * PAIRS_PER_SPLIT + lane;
    int gbase = 2 * (split * PAIRS_PER_SPLIT + lane);

    #pragma unroll 8
    for (int it = 0; it < ITERS; it++) {
        const float4 v = gp[it * 32];
        const int g = gbase + it * 64;       // goals g, g+1

        // 4 independent accumulator chains (FMNMX dist-chain, SEL idx off-chain)
        {
            float d0 = fabsf(ax0 - v.x) + fabsf(ay0 - v.y);
            float d1 = fabsf(ax0 - v.z) + fabsf(ay0 - v.w);
            float m  = fminf(d0, d1);
            int   im = (d1 < d0) ? g + 1 : g;            // tie -> lower idx
            i0 = (m < b0) ? im : i0;
            b0 = fminf(b0, m);
        }
        {
            float d0 = fabsf(ax1 - v.x) + fabsf(ay1 - v.y);
            float d1 = fabsf(ax1 - v.z) + fabsf(ay1 - v.w);
            float m  = fminf(d0, d1);
            int   im = (d1 < d0) ? g + 1 : g;
            i1 = (m < b1) ? im : i1;
            b1 = fminf(b1, m);
        }
        {
            float d0 = fabsf(ax2 - v.x) + fabsf(ay2 - v.y);
            float d1 = fabsf(ax2 - v.z) + fabsf(ay2 - v.w);
            float m  = fminf(d0, d1);
            int   im = (d1 < d0) ? g + 1 : g;
            i2 = (m < b2) ? im : i2;
            b2 = fminf(b2, m);
        }
        {
            float d0 = fabsf(ax3 - v.x) + fabsf(ay3 - v.y);
            float d1 = fabsf(ax3 - v.z) + fabsf(ay3 - v.w);
            float m  = fminf(d0, d1);
            int   im = (d1 < d0) ? g + 1 : g;
            i3 = (m < b3) ? im : i3;
            b3 = fminf(b3, m);
        }
    }

    // Warp reduction per agent: lexicographic (dist, idx) min.
    const unsigned mask = 0xffffffffu;
    float bb[AGW] = {b0, b1, b2, b3};
    int   ii[AGW] = {i0, i1, i2, i3};

    #pragma unroll
    for (int j = 0; j < AGW; j++) {
        float best = bb[j];
        int   bi   = ii[j];
        #pragma unroll
        for (int off = 16; off; off >>= 1) {
            float od = __shfl_xor_sync(mask, best, off);
            int   oi = __shfl_xor_sync(mask, bi,   off);
            if (od < best || (od == best && oi < bi)) { best = od; bi = oi; }
        }
        if (lane == 0) {
            const int s = (group * AGW + j) * SPLITS + split;
            sd[s] = best;
            si[s] = bi;
        }
    }

    __syncthreads();

    // One thread per agent merges the 4 split partials and runs the policy.
    if (tid < AGB) {
        const int base = tid * SPLITS;
        float best = sd[base];
        int   bi   = si[base];
        #pragma unroll
        for (int s = 1; s < SPLITS; s++) {
            float od = sd[base + s];
            int   oi = si[base + s];
            if (od < best || (od == best && oi < bi)) { best = od; bi = oi; }
        }

        const int agent = blockIdx.x * AGB + tid;
        const float ax = x[3 * agent];
        const float ay = x[3 * agent + 1];
        const float2 gsel = reinterpret_cast<const float2*>(g_goals4)[bi];
        float dx = gsel.x - ax;
        float dy = gsel.y - ay;

        // probs = [dx>0, dx<0, dy>0, dy<0, (dx==0)&(dy==0)]; cdf = cumsum
        float c0 = (dx > 0.0f) ? 1.0f : 0.0f;
        float c1 = c0 + ((dx < 0.0f) ? 1.0f : 0.0f);
        float c2 = c1 + ((dy > 0.0f) ? 1.0f : 0.0f);
        float c3 = c2 + ((dy < 0.0f) ? 1.0f : 0.0f);
        float c4 = c3 + ((dx == 0.0f && dy == 0.0f) ? 1.0f : 0.0f);

        float t = u[agent] * c4;

        int act = 4;
        if      (c0 >= t) act = 0;
        else if (c1 >= t) act = 1;
        else if (c2 >= t) act = 2;
        else if (c3 >= t) act = 3;

        out[agent] = (float)act;   // output dtype is float32
    }
}

extern "C" void kernel_launch(void* const* d_in, const int* in_sizes, int n_in,
                              void* d_out, int out_size)
{
    // Size-driven binding (element counts): x = 6*N, u = N.
    const float* x = nullptr;
    const float* u = nullptr;
    for (int i = 0; i < n_in; i++) {
        if (in_sizes[i] == 6 * N_AGENTS)      x = (const float*)d_in[i];
        else if (in_sizes[i] == N_AGENTS)     u = (const float*)d_in[i];
    }
    if (!x) x = (const float*)d_in[0];
    if (!u) u = (const float*)d_in[n_in > 1 ? 1 : 0];

    float* out = (float*)d_out;

    pack_goals_kernel<<<N_AGENTS / 256, 256>>>(x);
    rollout_policy_kernel<<<NBLOCKS, THREADS>>>(x, u, out);
    (void)out_size;
}